// round 4
// baseline (speedup 1.0000x reference)
#include <cuda_runtime.h>

typedef unsigned long long ull;

// Problem constants
#define Bsz    32768
#define Tt     7
#define Ff     36
#define Uu     256
#define KK     292          // Uu + Ff contraction length
#define BM     32           // batch rows per CTA (== warp width)
#define NT     512          // 16 warps
#define NW     16
#define TILE   32           // k-rows per weight tile
#define NTILE  10           // 9*32 + 4 = 292
#define NBUF   3
#define MPAD   33           // padded m row -> conflict-free in both directions

#define M_FLOATS  (KK * MPAD)
#define M_BYTES   (((M_FLOATS * 4) + 127) & ~127)
#define WBUF_BYTES (NBUF * TILE * 128 * 8)          // 3 * 32KB
#define SMEM_TOTAL (M_BYTES + WBUF_BYTES)           // ~137 KB

// ---------------------------------------------------------------------------
// helpers
// ---------------------------------------------------------------------------
__device__ __forceinline__ ull dup2(float a) {
    ull r; asm("mov.b64 %0, {%1, %1};" : "=l"(r) : "f"(a)); return r;
}
__device__ __forceinline__ void unpk(ull v, float& a, float& b) {
    asm("mov.b64 {%0, %1}, %2;" : "=f"(a), "=f"(b) : "l"(v));
}
__device__ __forceinline__ void ffma2(ull& d, ull a, ull b) {
    asm("fma.rn.f32x2 %0, %1, %2, %0;" : "+l"(d) : "l"(a), "l"(b));
}
__device__ __forceinline__ float fsgm(float z) {
    float e, r;
    asm("ex2.approx.f32 %0, %1;" : "=f"(e) : "f"(-1.4426950408889634f * z));
    asm("rcp.approx.f32 %0, %1;" : "=f"(r) : "f"(1.0f + e));
    return r;
}
__device__ __forceinline__ float ftanh(float z) {
    float e, r;
    asm("ex2.approx.f32 %0, %1;" : "=f"(e) : "f"(-2.8853900817779268f * z));
    asm("rcp.approx.f32 %0, %1;" : "=f"(r) : "f"(1.0f + e));
    return fmaf(2.0f, r, -1.0f);
}
__device__ __forceinline__ void cp_async16(void* smem_dst, const void* gsrc) {
    unsigned s = (unsigned)__cvta_generic_to_shared(smem_dst);
    asm volatile("cp.async.cg.shared.global [%0], [%1], 16;" :: "r"(s), "l"(gsrc));
}
__device__ __forceinline__ void cp_commit() {
    asm volatile("cp.async.commit_group;" ::: "memory");
}
__device__ __forceinline__ void cp_wait1() {
    asm volatile("cp.async.wait_group 1;" ::: "memory");
}
__device__ __forceinline__ void cp_wait0() {
    asm volatile("cp.async.wait_group 0;" ::: "memory");
}

// ---------------------------------------------------------------------------
// stage weight tile i (TILE k-rows x 256 gate cols, 1KB/row) into wbuf[buf]
// k < 256 -> Wr rows; k >= 256 -> Wk rows. Tiles never straddle (256 % 32 == 0).
// ---------------------------------------------------------------------------
__device__ __forceinline__ void copy_tile(
    int i, int buf, int gate, int tid,
    const float* __restrict__ Wr, const float* __restrict__ Wk,
    ull (*__restrict__ wbuf)[TILE][128])
{
    const int k0 = i * TILE;
    const float* src;
    int kb;
    if (k0 < Uu) { src = Wr; kb = k0; }
    else         { src = Wk; kb = k0 - Uu; }
    const int cnt   = (KK - k0) < TILE ? (KK - k0) : TILE;  // 32 or 4
    const int units = cnt * 64;                             // 16B units
#pragma unroll 1
    for (int u = tid; u < units; u += NT) {
        int kk = u >> 6, ch = u & 63;
        cp_async16(&wbuf[buf][kk][ch * 2],
                   src + (size_t)(kb + kk) * 1024 + gate * 256 + ch * 4);
    }
    cp_commit();
}

// ---------------------------------------------------------------------------
// compute tile: acc[j] += m[k][lane] * W[k][16w+2j .. +1]   (broadcast weights)
// ---------------------------------------------------------------------------
__device__ __forceinline__ void compute_tile(
    int i, int buf, int w, int lane,
    const float (*__restrict__ m_sh)[MPAD],
    const ull (*__restrict__ wbuf)[TILE][128],
    ull acc[8])
{
    const int k0  = i * TILE;
    const int cnt = (KK - k0) < TILE ? (KK - k0) : TILE;
#pragma unroll 4
    for (int kk = 0; kk < cnt; kk++) {
        ull m2 = dup2(m_sh[k0 + kk][lane]);
        const ull* row = &wbuf[buf][kk][8 * w];
        ulonglong2 wA = *reinterpret_cast<const ulonglong2*>(row);
        ulonglong2 wB = *reinterpret_cast<const ulonglong2*>(row + 2);
        ulonglong2 wC = *reinterpret_cast<const ulonglong2*>(row + 4);
        ulonglong2 wD = *reinterpret_cast<const ulonglong2*>(row + 6);
        ffma2(acc[0], m2, wA.x); ffma2(acc[1], m2, wA.y);
        ffma2(acc[2], m2, wB.x); ffma2(acc[3], m2, wB.y);
        ffma2(acc[4], m2, wC.x); ffma2(acc[5], m2, wC.y);
        ffma2(acc[6], m2, wD.x); ffma2(acc[7], m2, wD.y);
    }
}

// ---------------------------------------------------------------------------
// one full gate sweep over k = 0..291 with triple-buffered weight tiles
// ---------------------------------------------------------------------------
__device__ __forceinline__ void gate_sweep(
    int gate, int w, int lane, int tid,
    const float* __restrict__ Wr, const float* __restrict__ Wk,
    const ull* __restrict__ b2u,
    const float (*__restrict__ m_sh)[MPAD],
    ull (*__restrict__ wbuf)[TILE][128],
    ull acc[8])
{
#pragma unroll
    for (int j = 0; j < 8; j++)
        acc[j] = b2u[gate * 128 + 8 * w + j];

    // previous sweep's last compute (and m_sh writers) must be done
    __syncthreads();
    copy_tile(0, 0, gate, tid, Wr, Wk, wbuf);
    copy_tile(1, 1, gate, tid, Wr, Wk, wbuf);

#pragma unroll 1
    for (int i = 0; i < NTILE; i++) {
        if (i + 1 < NTILE) cp_wait1(); else cp_wait0();
        __syncthreads();   // tile i visible; all threads done compute(i-1)
        if (i + 2 < NTILE)
            copy_tile(i + 2, (i + 2) % NBUF, gate, tid, Wr, Wk, wbuf);
        compute_tile(i, i % NBUF, w, lane, m_sh, wbuf, acc);
    }
}

// ---------------------------------------------------------------------------
// LSTM kernel: 1 CTA = 32 batch rows, 16 warps; lane = batch row.
// warp w owns gate-columns [16w, 16w+16) of each gate.
// ---------------------------------------------------------------------------
__global__ void __launch_bounds__(NT, 1)
lstm_kernel(const float* __restrict__ x,   // [B,T,F]
            const float* __restrict__ h0,  // [B,U]
            const float* __restrict__ c0,  // [B,U]
            const float* __restrict__ Wk,  // [F,4U]
            const float* __restrict__ Wr,  // [U,4U]
            const float* __restrict__ b,   // [4U]
            float* __restrict__ out)       // [B,T,U]
{
    extern __shared__ char smraw[];
    float (*m_sh)[MPAD] = reinterpret_cast<float(*)[MPAD]>(smraw);
    ull (*wbuf)[TILE][128] =
        reinterpret_cast<ull(*)[TILE][128]>(smraw + M_BYTES);

    const int tid  = threadIdx.x;
    const int lane = tid & 31;
    const int w    = tid >> 5;
    const int row0 = blockIdx.x * BM;

    // ---- h0 -> m_sh[u][r] (coalesced LDG, conflict-free STS via MPAD=33) ----
#pragma unroll 1
    for (int i = tid; i < BM * Uu; i += NT) {
        int r = i >> 8, u = i & 255;
        m_sh[u][r] = h0[(size_t)(row0 + r) * Uu + u];
    }
    // ---- x(t=0) -> m_sh[256+f][r] ----
#pragma unroll 1
    for (int i = tid; i < BM * Ff; i += NT) {
        int r = i / Ff, f = i - r * Ff;
        m_sh[Uu + f][r] = x[(size_t)(row0 + r) * (Tt * Ff) + f];
    }

    // ---- c0 -> registers: lane's row, cols 16w..16w+15 ----
    float c[16];
    {
        const float4* c4 = reinterpret_cast<const float4*>(
            c0 + (size_t)(row0 + lane) * Uu + 16 * w);
#pragma unroll
        for (int q = 0; q < 4; q++) {
            float4 v = c4[q];
            c[4 * q] = v.x; c[4 * q + 1] = v.y;
            c[4 * q + 2] = v.z; c[4 * q + 3] = v.w;
        }
    }

    const ull* __restrict__ b2u = reinterpret_cast<const ull*>(b);

    float gv[16], h[16];
    ull acc[8];

#pragma unroll 1
    for (int t = 0; t < Tt; t++) {
        // ---- gate g: gv = tanh(z_g) ----
        gate_sweep(2, w, lane, tid, Wr, Wk, b2u, m_sh, wbuf, acc);
#pragma unroll
        for (int j = 0; j < 8; j++) {
            float z0, z1; unpk(acc[j], z0, z1);
            gv[2 * j]     = ftanh(z0);
            gv[2 * j + 1] = ftanh(z1);
        }
        // ---- gate i: gv *= sigmoid(z_i) ----
        gate_sweep(0, w, lane, tid, Wr, Wk, b2u, m_sh, wbuf, acc);
#pragma unroll
        for (int j = 0; j < 8; j++) {
            float z0, z1; unpk(acc[j], z0, z1);
            gv[2 * j]     *= fsgm(z0);
            gv[2 * j + 1] *= fsgm(z1);
        }
        // ---- gate f: c = sigmoid(z_f)*c + gv ; gv = tanh(c) ----
        gate_sweep(1, w, lane, tid, Wr, Wk, b2u, m_sh, wbuf, acc);
#pragma unroll
        for (int j = 0; j < 8; j++) {
            float z0, z1; unpk(acc[j], z0, z1);
            c[2 * j]     = fsgm(z0) * c[2 * j]     + gv[2 * j];
            c[2 * j + 1] = fsgm(z1) * c[2 * j + 1] + gv[2 * j + 1];
            gv[2 * j]     = ftanh(c[2 * j]);
            gv[2 * j + 1] = ftanh(c[2 * j + 1]);
        }
        // ---- gate o: h = sigmoid(z_o) * gv ----
        gate_sweep(3, w, lane, tid, Wr, Wk, b2u, m_sh, wbuf, acc);
#pragma unroll
        for (int j = 0; j < 8; j++) {
            float z0, z1; unpk(acc[j], z0, z1);
            h[2 * j]     = fsgm(z0) * gv[2 * j];
            h[2 * j + 1] = fsgm(z1) * gv[2 * j + 1];
        }

        // all o-sweep reads of m_sh complete before h overwrites it
        __syncthreads();

        // publish h -> m_sh (conflict-free: lanes consecutive per column)
#pragma unroll
        for (int j = 0; j < 16; j++)
            m_sh[16 * w + j][lane] = h[j];

        // stream h to out: lane's row, 64B contiguous
        {
            float4* o4 = reinterpret_cast<float4*>(
                out + (((size_t)(row0 + lane)) * Tt + t) * Uu + 16 * w);
#pragma unroll
            for (int q = 0; q < 4; q++)
                o4[q] = make_float4(h[4 * q], h[4 * q + 1],
                                    h[4 * q + 2], h[4 * q + 3]);
        }

        // x(t+1) -> m_sh (visibility guaranteed by next sweep's entry sync)
        if (t + 1 < Tt) {
#pragma unroll 1
            for (int i = tid; i < BM * Ff; i += NT) {
                int r = i / Ff, f = i - r * Ff;
                m_sh[Uu + f][r] =
                    x[((size_t)(row0 + r) * Tt + (t + 1)) * Ff + f];
            }
        }
    }
}

// ---------------------------------------------------------------------------
// Harness entry point
// ---------------------------------------------------------------------------
extern "C" void kernel_launch(void* const* d_in, const int* in_sizes, int n_in,
                              void* d_out, int out_size) {
    const float* x  = (const float*)d_in[0];  // [B,T,F]
    const float* h0 = (const float*)d_in[1];  // [B,U]
    const float* c0 = (const float*)d_in[2];  // [B,U]
    const float* Wk = (const float*)d_in[3];  // [F,4U]
    const float* Wr = (const float*)d_in[4];  // [U,4U]
    const float* b  = (const float*)d_in[5];  // [4U]
    float* out = (float*)d_out;               // [B,T,U]

    cudaFuncSetAttribute(lstm_kernel,
                         cudaFuncAttributeMaxDynamicSharedMemorySize,
                         SMEM_TOTAL);
    lstm_kernel<<<Bsz / BM, NT, SMEM_TOTAL>>>(x, h0, c0, Wk, Wr, b, out);
}

// round 5
// speedup vs baseline: 1.0009x; 1.0009x over previous
#include <cuda_runtime.h>

typedef unsigned long long ull;

// Problem constants
#define Bsz    32768
#define Tt     7
#define Ff     36
#define Uu     256
#define KK     292          // Uu + Ff contraction length
#define BM     32           // batch rows per CTA (== warp width)
#define NT     512          // 16 warps
#define NW     16
#define TILE   32           // k-rows per weight tile
#define NTILE  10           // 9*32 + 4 = 292
#define NBUF   3
#define MPAD   33           // padded m row -> conflict-free in both directions

#define M_FLOATS  (KK * MPAD)
#define M_BYTES   (((M_FLOATS * 4) + 127) & ~127)
#define WBUF_BYTES (NBUF * TILE * 128 * 8)          // 3 * 32KB
#define SMEM_TOTAL (M_BYTES + WBUF_BYTES)           // ~137 KB

// ---------------------------------------------------------------------------
// helpers
// ---------------------------------------------------------------------------
__device__ __forceinline__ ull dup2(float a) {
    ull r; asm("mov.b64 %0, {%1, %1};" : "=l"(r) : "f"(a)); return r;
}
__device__ __forceinline__ void unpk(ull v, float& a, float& b) {
    asm("mov.b64 {%0, %1}, %2;" : "=f"(a), "=f"(b) : "l"(v));
}
__device__ __forceinline__ void ffma2(ull& d, ull a, ull b) {
    asm("fma.rn.f32x2 %0, %1, %2, %0;" : "+l"(d) : "l"(a), "l"(b));
}
__device__ __forceinline__ float fsgm(float z) {
    float e, r;
    asm("ex2.approx.f32 %0, %1;" : "=f"(e) : "f"(-1.4426950408889634f * z));
    asm("rcp.approx.f32 %0, %1;" : "=f"(r) : "f"(1.0f + e));
    return r;
}
__device__ __forceinline__ float ftanh(float z) {
    float e, r;
    asm("ex2.approx.f32 %0, %1;" : "=f"(e) : "f"(-2.8853900817779268f * z));
    asm("rcp.approx.f32 %0, %1;" : "=f"(r) : "f"(1.0f + e));
    return fmaf(2.0f, r, -1.0f);
}
__device__ __forceinline__ void cp_async16(void* smem_dst, const void* gsrc) {
    unsigned s = (unsigned)__cvta_generic_to_shared(smem_dst);
    asm volatile("cp.async.cg.shared.global [%0], [%1], 16;" :: "r"(s), "l"(gsrc));
}
__device__ __forceinline__ void cp_commit() {
    asm volatile("cp.async.commit_group;" ::: "memory");
}
__device__ __forceinline__ void cp_wait1() {
    asm volatile("cp.async.wait_group 1;" ::: "memory");
}
__device__ __forceinline__ void cp_wait0() {
    asm volatile("cp.async.wait_group 0;" ::: "memory");
}

// ---------------------------------------------------------------------------
// stage weight tile i (TILE k-rows x 256 gate cols, 1KB/row) into wbuf[buf]
// k < 256 -> Wr rows; k >= 256 -> Wk rows. Tiles never straddle (256 % 32 == 0).
// ---------------------------------------------------------------------------
__device__ __forceinline__ void copy_tile(
    int i, int buf, int gate, int tid,
    const float* __restrict__ Wr, const float* __restrict__ Wk,
    ull (*__restrict__ wbuf)[TILE][128])
{
    const int k0 = i * TILE;
    const float* src;
    int kb;
    if (k0 < Uu) { src = Wr; kb = k0; }
    else         { src = Wk; kb = k0 - Uu; }
    const int cnt   = (KK - k0) < TILE ? (KK - k0) : TILE;  // 32 or 4
    const int units = cnt * 64;                             // 16B units
#pragma unroll 1
    for (int u = tid; u < units; u += NT) {
        int kk = u >> 6, ch = u & 63;
        cp_async16(&wbuf[buf][kk][ch * 2],
                   src + (size_t)(kb + kk) * 1024 + gate * 256 + ch * 4);
    }
    cp_commit();
}

// ---------------------------------------------------------------------------
// compute tile: acc[j] += m[k][lane] * W[k][16w+2j .. +1]   (broadcast weights)
// ---------------------------------------------------------------------------
__device__ __forceinline__ void compute_tile(
    int i, int buf, int w, int lane,
    const float (*__restrict__ m_sh)[MPAD],
    const ull (*__restrict__ wbuf)[TILE][128],
    ull acc[8])
{
    const int k0  = i * TILE;
    const int cnt = (KK - k0) < TILE ? (KK - k0) : TILE;
#pragma unroll 4
    for (int kk = 0; kk < cnt; kk++) {
        ull m2 = dup2(m_sh[k0 + kk][lane]);
        const ull* row = &wbuf[buf][kk][8 * w];
        ulonglong2 wA = *reinterpret_cast<const ulonglong2*>(row);
        ulonglong2 wB = *reinterpret_cast<const ulonglong2*>(row + 2);
        ulonglong2 wC = *reinterpret_cast<const ulonglong2*>(row + 4);
        ulonglong2 wD = *reinterpret_cast<const ulonglong2*>(row + 6);
        ffma2(acc[0], m2, wA.x); ffma2(acc[1], m2, wA.y);
        ffma2(acc[2], m2, wB.x); ffma2(acc[3], m2, wB.y);
        ffma2(acc[4], m2, wC.x); ffma2(acc[5], m2, wC.y);
        ffma2(acc[6], m2, wD.x); ffma2(acc[7], m2, wD.y);
    }
}

// ---------------------------------------------------------------------------
// one full gate sweep over k = 0..291 with triple-buffered weight tiles
// ---------------------------------------------------------------------------
__device__ __forceinline__ void gate_sweep(
    int gate, int w, int lane, int tid,
    const float* __restrict__ Wr, const float* __restrict__ Wk,
    const ull* __restrict__ b2u,
    const float (*__restrict__ m_sh)[MPAD],
    ull (*__restrict__ wbuf)[TILE][128],
    ull acc[8])
{
#pragma unroll
    for (int j = 0; j < 8; j++)
        acc[j] = b2u[gate * 128 + 8 * w + j];

    // previous sweep's last compute (and m_sh writers) must be done
    __syncthreads();
    copy_tile(0, 0, gate, tid, Wr, Wk, wbuf);
    copy_tile(1, 1, gate, tid, Wr, Wk, wbuf);

#pragma unroll 1
    for (int i = 0; i < NTILE; i++) {
        if (i + 1 < NTILE) cp_wait1(); else cp_wait0();
        __syncthreads();   // tile i visible; all threads done compute(i-1)
        if (i + 2 < NTILE)
            copy_tile(i + 2, (i + 2) % NBUF, gate, tid, Wr, Wk, wbuf);
        compute_tile(i, i % NBUF, w, lane, m_sh, wbuf, acc);
    }
}

// ---------------------------------------------------------------------------
// LSTM kernel: 1 CTA = 32 batch rows, 16 warps; lane = batch row.
// warp w owns gate-columns [16w, 16w+16) of each gate.
// ---------------------------------------------------------------------------
__global__ void __launch_bounds__(NT, 1)
lstm_kernel(const float* __restrict__ x,   // [B,T,F]
            const float* __restrict__ h0,  // [B,U]
            const float* __restrict__ c0,  // [B,U]
            const float* __restrict__ Wk,  // [F,4U]
            const float* __restrict__ Wr,  // [U,4U]
            const float* __restrict__ b,   // [4U]
            float* __restrict__ out)       // [B,T,U]
{
    extern __shared__ char smraw[];
    float (*m_sh)[MPAD] = reinterpret_cast<float(*)[MPAD]>(smraw);
    ull (*wbuf)[TILE][128] =
        reinterpret_cast<ull(*)[TILE][128]>(smraw + M_BYTES);

    const int tid  = threadIdx.x;
    const int lane = tid & 31;
    const int w    = tid >> 5;
    const int row0 = blockIdx.x * BM;

    // ---- h0 -> m_sh[u][r] (coalesced LDG, conflict-free STS via MPAD=33) ----
#pragma unroll 1
    for (int i = tid; i < BM * Uu; i += NT) {
        int r = i >> 8, u = i & 255;
        m_sh[u][r] = h0[(size_t)(row0 + r) * Uu + u];
    }
    // ---- x(t=0) -> m_sh[256+f][r] ----
#pragma unroll 1
    for (int i = tid; i < BM * Ff; i += NT) {
        int r = i / Ff, f = i - r * Ff;
        m_sh[Uu + f][r] = x[(size_t)(row0 + r) * (Tt * Ff) + f];
    }

    // ---- c0 -> registers: lane's row, cols 16w..16w+15 ----
    float c[16];
    {
        const float4* c4 = reinterpret_cast<const float4*>(
            c0 + (size_t)(row0 + lane) * Uu + 16 * w);
#pragma unroll
        for (int q = 0; q < 4; q++) {
            float4 v = c4[q];
            c[4 * q] = v.x; c[4 * q + 1] = v.y;
            c[4 * q + 2] = v.z; c[4 * q + 3] = v.w;
        }
    }

    const ull* __restrict__ b2u = reinterpret_cast<const ull*>(b);

    float gv[16], h[16];
    ull acc[8];

#pragma unroll 1
    for (int t = 0; t < Tt; t++) {
        // ---- gate g: gv = tanh(z_g) ----
        gate_sweep(2, w, lane, tid, Wr, Wk, b2u, m_sh, wbuf, acc);
#pragma unroll
        for (int j = 0; j < 8; j++) {
            float z0, z1; unpk(acc[j], z0, z1);
            gv[2 * j]     = ftanh(z0);
            gv[2 * j + 1] = ftanh(z1);
        }
        // ---- gate i: gv *= sigmoid(z_i) ----
        gate_sweep(0, w, lane, tid, Wr, Wk, b2u, m_sh, wbuf, acc);
#pragma unroll
        for (int j = 0; j < 8; j++) {
            float z0, z1; unpk(acc[j], z0, z1);
            gv[2 * j]     *= fsgm(z0);
            gv[2 * j + 1] *= fsgm(z1);
        }
        // ---- gate f: c = sigmoid(z_f)*c + gv ; gv = tanh(c) ----
        gate_sweep(1, w, lane, tid, Wr, Wk, b2u, m_sh, wbuf, acc);
#pragma unroll
        for (int j = 0; j < 8; j++) {
            float z0, z1; unpk(acc[j], z0, z1);
            c[2 * j]     = fsgm(z0) * c[2 * j]     + gv[2 * j];
            c[2 * j + 1] = fsgm(z1) * c[2 * j + 1] + gv[2 * j + 1];
            gv[2 * j]     = ftanh(c[2 * j]);
            gv[2 * j + 1] = ftanh(c[2 * j + 1]);
        }
        // ---- gate o: h = sigmoid(z_o) * gv ----
        gate_sweep(3, w, lane, tid, Wr, Wk, b2u, m_sh, wbuf, acc);
#pragma unroll
        for (int j = 0; j < 8; j++) {
            float z0, z1; unpk(acc[j], z0, z1);
            h[2 * j]     = fsgm(z0) * gv[2 * j];
            h[2 * j + 1] = fsgm(z1) * gv[2 * j + 1];
        }

        // all o-sweep reads of m_sh complete before h overwrites it
        __syncthreads();

        // publish h -> m_sh (conflict-free: lanes consecutive per column)
#pragma unroll
        for (int j = 0; j < 16; j++)
            m_sh[16 * w + j][lane] = h[j];

        // stream h to out: lane's row, 64B contiguous
        {
            float4* o4 = reinterpret_cast<float4*>(
                out + (((size_t)(row0 + lane)) * Tt + t) * Uu + 16 * w);
#pragma unroll
            for (int q = 0; q < 4; q++)
                o4[q] = make_float4(h[4 * q], h[4 * q + 1],
                                    h[4 * q + 2], h[4 * q + 3]);
        }

        // x(t+1) -> m_sh (visibility guaranteed by next sweep's entry sync)
        if (t + 1 < Tt) {
#pragma unroll 1
            for (int i = tid; i < BM * Ff; i += NT) {
                int r = i / Ff, f = i - r * Ff;
                m_sh[Uu + f][r] =
                    x[((size_t)(row0 + r) * Tt + (t + 1)) * Ff + f];
            }
        }
    }
}

// ---------------------------------------------------------------------------
// Harness entry point
// ---------------------------------------------------------------------------
extern "C" void kernel_launch(void* const* d_in, const int* in_sizes, int n_in,
                              void* d_out, int out_size) {
    const float* x  = (const float*)d_in[0];  // [B,T,F]
    const float* h0 = (const float*)d_in[1];  // [B,U]
    const float* c0 = (const float*)d_in[2];  // [B,U]
    const float* Wk = (const float*)d_in[3];  // [F,4U]
    const float* Wr = (const float*)d_in[4];  // [U,4U]
    const float* b  = (const float*)d_in[5];  // [4U]
    float* out = (float*)d_out;               // [B,T,U]

    cudaFuncSetAttribute(lstm_kernel,
                         cudaFuncAttributeMaxDynamicSharedMemorySize,
                         SMEM_TOTAL);
    lstm_kernel<<<Bsz / BM, NT, SMEM_TOTAL>>>(x, h0, c0, Wk, Wr, b, out);
}

// round 8
// speedup vs baseline: 2.0595x; 2.0577x over previous
#include <cuda_runtime.h>
#include <cuda_bf16.h>

typedef unsigned int u32;

// ---------------- problem constants ----------------
#define Tt   7
#define Ff   36
#define Uu   256
#define Bsz  32768
#define BMr  64             // batch rows per CTA (2 m-warp rows x 32)
#define NTm  512            // 16 warps = 2M x 8N
#define NCTA 512            // Bsz / BMr
#define KPAD 304            // 256 h + 36 x + 12 pad = 19 k16 chunks
#define NCH  19
#define SPAD 312            // A row stride in bf16 (conflict-stagger + 16B mult)
#define ROWB (SPAD * 2)     // 624 bytes per A row
#define CHUNKS_PER_STEP 152 // 8 passes x 19 chunks
#define TOTAL_CHUNKS (Tt * CHUNKS_PER_STEP)   // 1064

// ---------------- smem layout ----------------
#define AH_OFF 0
#define AL_OFF (BMr * ROWB)           // 39936
#define B_OFF  (2 * BMr * ROWB)       // 79872
#define STG_SZ 8192                   // one B chunk (hi+lo, frag-ordered)
#define SMEM_TOTAL (B_OFF + 4 * STG_SZ)   // 112640 (110 KB)

// ---------------- device scratch (static) ----------------
__device__ u32   g_Bfrag[8 * NCH * 2 * 1024];         // frag-ordered B chunks (1.2MB)
__device__ float g_c[(size_t)32 * NCTA * NTm];        // c state scratch
__constant__ int c_pord[8] = {4, 0, 2, 6, 5, 1, 3, 7}; // pass order: g,i,f,o per half

// ---------------- ptx helpers ----------------
__device__ __forceinline__ u32 smem_u32(const void* p) {
    u32 a;
    asm("{ .reg .u64 t; cvta.to.shared.u64 t, %1; cvt.u32.u64 %0, t; }"
        : "=r"(a) : "l"(p));
    return a;
}
__device__ __forceinline__ float fsgm(float z) {
    float e, r;
    asm("ex2.approx.f32 %0, %1;" : "=f"(e) : "f"(-1.4426950408889634f * z));
    asm("rcp.approx.f32 %0, %1;" : "=f"(r) : "f"(1.0f + e));
    return r;
}
__device__ __forceinline__ float ftanh(float z) {
    float e, r;
    asm("ex2.approx.f32 %0, %1;" : "=f"(e) : "f"(-2.8853900817779268f * z));
    asm("rcp.approx.f32 %0, %1;" : "=f"(r) : "f"(1.0f + e));
    return fmaf(2.0f, r, -1.0f);
}
__device__ __forceinline__ void cp_async16(u32 saddr, const void* g) {
    asm volatile("cp.async.cg.shared.global [%0], [%1], 16;" :: "r"(saddr), "l"(g));
}
#define CP_COMMIT() asm volatile("cp.async.commit_group;" ::: "memory")
#define CP_WAIT2()  asm volatile("cp.async.wait_group 2;" ::: "memory")
#define CP_WAIT1()  asm volatile("cp.async.wait_group 1;" ::: "memory")
#define CP_WAIT0()  asm volatile("cp.async.wait_group 0;" ::: "memory")
__device__ __forceinline__ void ldm4(u32* r, u32 addr) {
    asm volatile("ldmatrix.sync.aligned.m8n8.x4.shared.b16 {%0,%1,%2,%3}, [%4];"
                 : "=r"(r[0]), "=r"(r[1]), "=r"(r[2]), "=r"(r[3]) : "r"(addr));
}
__device__ __forceinline__ void lds128(u32* r, u32 addr) {
    asm volatile("ld.shared.v4.u32 {%0,%1,%2,%3}, [%4];"
                 : "=r"(r[0]), "=r"(r[1]), "=r"(r[2]), "=r"(r[3]) : "r"(addr));
}
__device__ __forceinline__ void mma16816(float* d, const u32* a, const u32* b) {
    asm volatile(
        "mma.sync.aligned.m16n8k16.row.col.f32.bf16.bf16.f32 "
        "{%0,%1,%2,%3}, {%4,%5,%6,%7}, {%8,%9}, {%0,%1,%2,%3};"
        : "+f"(d[0]), "+f"(d[1]), "+f"(d[2]), "+f"(d[3])
        : "r"(a[0]), "r"(a[1]), "r"(a[2]), "r"(a[3]), "r"(b[0]), "r"(b[1]));
}

// A store helper: split fp32 into bf16 hi/lo at A[r][k]
__device__ __forceinline__ void a_store(char* sm, int r, int k, float v) {
    __nv_bfloat16 hi = __float2bfloat16(v);
    __nv_bfloat16 lo = __float2bfloat16(v - __bfloat162float(hi));
    int off = r * ROWB + k * 2;
    *reinterpret_cast<__nv_bfloat16*>(sm + AH_OFF + off) = hi;
    *reinterpret_cast<__nv_bfloat16*>(sm + AL_OFF + off) = lo;
}

// ---------------------------------------------------------------------------
// prep: pack W = [Wr;Wk;0] into mma B-fragment order, bf16 hi/lo.
// u32 index: ((p*19+cc)*2+term)*1024 + wn*128 + lane*4 + reg
//   p = gate*2+half, reg = nt*2 + khalf; element pair (k0, k0+1):
//   n   = (p&1)*128 + wn*16 + nt*8 + (lane>>2)
//   k0  = cc*16 + khalf*8 + 2*(lane&3)
// ---------------------------------------------------------------------------
__global__ void prep_kernel(const float* __restrict__ Wr,
                            const float* __restrict__ Wk) {
    int idx = blockIdx.x * 512 + threadIdx.x;
    if (idx >= 8 * NCH * 2 * 1024) return;
    int reg  = idx & 3;
    int lane = (idx >> 2) & 31;
    int wn   = (idx >> 7) & 7;
    int rest = idx >> 10;
    int term = rest & 1;
    int pc   = rest >> 1;
    int cc   = pc % NCH;
    int p    = pc / NCH;

    int n    = (p & 1) * 128 + wn * 16 + (reg >> 1) * 8 + (lane >> 2);
    int ncol = (p >> 1) * 256 + n;
    int k0   = cc * 16 + (reg & 1) * 8 + ((lane & 3) << 1);

    float v0 = 0.f, v1 = 0.f;
    if (k0 < 256)      v0 = Wr[(size_t)k0 * 1024 + ncol];
    else if (k0 < 292) v0 = Wk[(size_t)(k0 - 256) * 1024 + ncol];
    int k1 = k0 + 1;
    if (k1 < 256)      v1 = Wr[(size_t)k1 * 1024 + ncol];
    else if (k1 < 292) v1 = Wk[(size_t)(k1 - 256) * 1024 + ncol];

    unsigned short e0, e1;
    if (term == 0) {
        e0 = __bfloat16_as_ushort(__float2bfloat16(v0));
        e1 = __bfloat16_as_ushort(__float2bfloat16(v1));
    } else {
        __nv_bfloat16 h0 = __float2bfloat16(v0);
        __nv_bfloat16 h1 = __float2bfloat16(v1);
        e0 = __bfloat16_as_ushort(__float2bfloat16(v0 - __bfloat162float(h0)));
        e1 = __bfloat16_as_ushort(__float2bfloat16(v1 - __bfloat162float(h1)));
    }
    g_Bfrag[idx] = ((u32)e1 << 16) | (u32)e0;
}

// ---------------------------------------------------------------------------
// main LSTM kernel: 512 CTAs x 512 threads (16 warps = 2M x 8N), HMMA mainloop
// ---------------------------------------------------------------------------
__global__ void __launch_bounds__(NTm, 1)
lstm_hmma(const float* __restrict__ x,    // [B,T,F]
          const float* __restrict__ h0,   // [B,U]
          const float* __restrict__ c0,   // [B,U]
          const float* __restrict__ bia,  // [4U]
          float* __restrict__ out)        // [B,T,U]
{
    extern __shared__ char sm[];
    const u32 smb  = smem_u32(sm);
    const int tid  = threadIdx.x;
    const int lane = tid & 31;
    const int wid  = tid >> 5;
    const int wm   = wid >> 3;       // 0..1  (M warp row: rows wm*32..+31)
    const int wn   = wid & 7;        // 0..7  (N warp col: cols wn*16..+15 of half)
    const int cta  = blockIdx.x;
    const int row0 = cta * BMr;

    // ---- init A: h0, x(t=0), zero pad ----
    for (int i = tid; i < BMr * Uu; i += NTm) {
        int r = i >> 8, k = i & 255;
        a_store(sm, r, k, h0[(size_t)(row0 + r) * Uu + k]);
    }
    for (int i = tid; i < BMr * Ff; i += NTm) {
        int r = i / Ff, f = i - r * Ff;
        a_store(sm, r, 256 + f, x[(size_t)(row0 + r) * (Tt * Ff) + f]);
    }
    for (int i = tid; i < BMr * (KPAD - 292); i += NTm) {
        int r = i / 12, k = 292 + (i - r * 12);
        a_store(sm, r, k, 0.0f);
    }
    __syncthreads();

    // ldmatrix per-lane base address (A hi, m-tile 0):
    // lanes 0-15 -> rows 0..15 k-low8; lanes 16-31 -> rows 0..15 k-high8
    const u32 aBase = smb + AH_OFF
                    + (u32)(wm * 32 + (lane & 15)) * ROWB
                    + (u32)((lane >> 4) * 16);

    // pipeline issue state
    int gi = 0;            // global chunks issued
    int qi = 0, cci = 0;   // (pass-in-step, chunk-in-pass) of next issue

    auto issue = [&]() {
        const char* src = reinterpret_cast<const char*>(g_Bfrag)
                        + ((size_t)(c_pord[qi] * NCH + cci)) * STG_SZ + tid * 16;
        cp_async16(smb + B_OFF + (gi & 3) * STG_SZ + tid * 16, src);
        CP_COMMIT();
        gi++;
        if (++cci == NCH) { cci = 0; if (++qi == 8) qi = 0; }
    };
    issue(); issue(); issue();

    float gv[16], hold[16];
    int gcons = 0;

#pragma unroll 1
    for (int t = 0; t < Tt; t++) {
#pragma unroll 1
        for (int q = 0; q < 8; q++) {
            const int pass = c_pord[q];
            const int gate = pass >> 1;
            const int half = pass & 1;

            float acc[2][2][4];
#pragma unroll
            for (int a = 0; a < 2; a++)
#pragma unroll
                for (int b = 0; b < 2; b++)
#pragma unroll
                    for (int e = 0; e < 4; e++) acc[a][b][e] = 0.f;

            // ---- mainloop: 19 k16 chunks ----
#pragma unroll 1
            for (int cc = 0; cc < NCH; cc++) {
                // pend-aware wait: guarantee chunk gcons is complete
                const int pend = gi - gcons;
                if (pend >= 3)      CP_WAIT2();
                else if (pend == 2) CP_WAIT1();
                else                CP_WAIT0();
                __syncthreads();
                if (gi < TOTAL_CHUNKS) issue();
                const int stg = gcons & 3; gcons++;

                const u32 ao = aBase + (u32)cc * 32;
                u32 ahi0[4], ahi1[4], alo0[4], alo1[4];
                ldm4(ahi0, ao);
                ldm4(ahi1, ao + 16 * ROWB);
                ldm4(alo0, ao + (AL_OFF - AH_OFF));
                ldm4(alo1, ao + (AL_OFF - AH_OFF) + 16 * ROWB);

                const u32 sb = smb + B_OFF + stg * STG_SZ + wn * 512 + lane * 16;
                u32 bh[4], bl[4];
                lds128(bh, sb);
                lds128(bl, sb + 4096);

#pragma unroll
                for (int nt = 0; nt < 2; nt++) {
                    mma16816(acc[0][nt], ahi0, &bh[nt * 2]);
                    mma16816(acc[1][nt], ahi1, &bh[nt * 2]);
                    mma16816(acc[0][nt], alo0, &bh[nt * 2]);
                    mma16816(acc[1][nt], alo1, &bh[nt * 2]);
                    mma16816(acc[0][nt], ahi0, &bl[nt * 2]);
                    mma16816(acc[1][nt], ahi1, &bl[nt * 2]);
                }
            }

            // ---- per-pass epilogue ----
            const int pk = q & 3;     // 0:g 1:i 2:f 3:o
#pragma unroll
            for (int j = 0; j < 16; j++) {
                const int mt = j >> 3, nt = (j >> 2) & 1, e = j & 3;
                const int ucol = half * 128 + wn * 16 + nt * 8
                               + 2 * (lane & 3) + (e & 1);
                const int row  = wm * 32 + mt * 16 + (lane >> 2) + ((e >> 1) << 3);
                const float z  = acc[mt][nt][e] + __ldg(bia + gate * 256 + ucol);
                if (pk == 0) {
                    gv[j] = ftanh(z);
                } else if (pk == 1) {
                    gv[j] *= fsgm(z);
                } else if (pk == 2) {
                    const size_t ci = (size_t)(half * 16 + j) * ((size_t)NCTA * NTm)
                                    + (size_t)cta * NTm + tid;
                    const float cold = (t == 0)
                        ? __ldg(c0 + (size_t)(row0 + row) * Uu + ucol)
                        : g_c[ci];
                    const float cn = fsgm(z) * cold + gv[j];
                    g_c[ci] = cn;
                    gv[j] = ftanh(cn);
                } else {
                    gv[j] = fsgm(z) * gv[j];   // h value
                }
            }

            if (pk == 3) {
                // write h to out (float2 pairs share a row)
#pragma unroll
                for (int jp = 0; jp < 8; jp++) {
                    const int j  = 2 * jp;
                    const int mt = j >> 3, nt = (j >> 2) & 1, e = j & 3;
                    const int ucol = half * 128 + wn * 16 + nt * 8 + 2 * (lane & 3);
                    const int row  = wm * 32 + mt * 16 + (lane >> 2) + ((e >> 1) << 3);
                    *reinterpret_cast<float2*>(
                        out + ((size_t)(row0 + row) * Tt + t) * Uu + ucol) =
                        make_float2(gv[j], gv[j + 1]);
                }
                if (half == 0) {
#pragma unroll
                    for (int j = 0; j < 16; j++) hold[j] = gv[j];
                }
            }
        } // q passes

        // ---- step boundary: write h (both halves) back into A, load x(t+1) ----
        __syncthreads();   // all A reads of this step complete
#pragma unroll
        for (int j = 0; j < 16; j++) {
            const int mt = j >> 3, nt = (j >> 2) & 1, e = j & 3;
            const int loc = wn * 16 + nt * 8 + 2 * (lane & 3) + (e & 1);
            const int row = wm * 32 + mt * 16 + (lane >> 2) + ((e >> 1) << 3);
            a_store(sm, row, 128 + loc, gv[j]);     // half 1
            a_store(sm, row, loc,       hold[j]);   // half 0
        }
        if (t + 1 < Tt) {
            for (int i = tid; i < BMr * Ff; i += NTm) {
                int r = i / Ff, f = i - r * Ff;
                a_store(sm, r, 256 + f,
                        x[((size_t)(row0 + r) * Tt + (t + 1)) * Ff + f]);
            }
        }
        __syncthreads();
    } // t
}

// ---------------------------------------------------------------------------
// Harness entry point
// ---------------------------------------------------------------------------
extern "C" void kernel_launch(void* const* d_in, const int* in_sizes, int n_in,
                              void* d_out, int out_size) {
    const float* x  = (const float*)d_in[0];  // [B,T,F]
    const float* h0 = (const float*)d_in[1];  // [B,U]
    const float* c0 = (const float*)d_in[2];  // [B,U]
    const float* Wk = (const float*)d_in[3];  // [F,4U]
    const float* Wr = (const float*)d_in[4];  // [U,4U]
    const float* b  = (const float*)d_in[5];  // [4U]
    float* out = (float*)d_out;               // [B,T,U]

    prep_kernel<<<(8 * NCH * 2 * 1024 + 511) / 512, 512>>>(Wr, Wk);

    cudaFuncSetAttribute(lstm_hmma,
                         cudaFuncAttributeMaxDynamicSharedMemorySize, SMEM_TOTAL);
    lstm_hmma<<<NCTA, NTm, SMEM_TOTAL>>>(x, h0, c0, b, out);
}